// round 15
// baseline (speedup 1.0000x reference)
#include <cuda_runtime.h>
#include <cuda_fp16.h>
#include <math.h>
#include <stdint.h>

#define BB 2
#define TT 2048
#define CC 768
#define HH 12
#define DD 64
#define MROWS (BB*TT)   // 4096
#define L2E 1.4426950408889634f

// ---------------- scratch ----------------------------------------------------
__device__ float g_res[(size_t)MROWS * CC];
__device__ float g_x1 [(size_t)MROWS * CC];
__device__ float g_x2 [(size_t)MROWS * CC];
__device__ __half g_x16  [(size_t)MROWS * CC];
__device__ __half g_enc16[(size_t)MROWS * CC];
__device__ __half g_qkv16[(size_t)MROWS * 3 * CC];
__device__ __half g_vt   [(size_t)BB * HH * DD * TT];   // V transposed [b][h][d][t]
__device__ __half g_att16[(size_t)MROWS * CC];
__device__ __half g_x1r  [(size_t)MROWS * CC];
__device__ __half g_x2r  [(size_t)MROWS * CC];
__device__ __half g_cq16 [(size_t)MROWS * CC];
__device__ __half g_ck16 [(size_t)MROWS * CC];
__device__ __half g_cvt  [(size_t)BB * HH * DD * TT];   // cross V transposed
__device__ __half g_h16  [(size_t)MROWS * 4 * CC];
// fp16 weights TRANSPOSED to [N][K], k-pair-packed as u32 [N][K/2]
__device__ uint32_t g_wq  [(size_t)3*CC * CC/2];
__device__ uint32_t g_wp  [(size_t)CC * CC/2];
__device__ uint32_t g_wcq [(size_t)CC * CC/2];
__device__ uint32_t g_wck [(size_t)CC * CC/2];
__device__ uint32_t g_wcv [(size_t)CC * CC/2];
__device__ uint32_t g_wco [(size_t)CC * CC/2];
__device__ uint32_t g_wfc [(size_t)4*CC * CC/2];
__device__ uint32_t g_wfc2[(size_t)CC * 4*CC/2];

enum { EPI_NONE = 0, EPI_RELU = 1, EPI_RES = 2 };
enum { OUT_F32 = 0, OUT_H = 1, OUT_QKV = 2, OUT_HP = 3 };

__device__ __forceinline__ void cp16(uint32_t s, const void* g) {
    asm volatile("cp.async.cg.shared.global [%0], [%1], 16;" :: "r"(s), "l"(g));
}
__device__ __forceinline__ void ldsm4(uint32_t* d, uint32_t addr) {
    asm volatile("ldmatrix.sync.aligned.m8n8.x4.shared.b16 {%0,%1,%2,%3}, [%4];"
        : "=r"(d[0]), "=r"(d[1]), "=r"(d[2]), "=r"(d[3]) : "r"(addr));
}
__device__ __forceinline__ void mma_f16(float* d, const uint32_t* a,
                                        uint32_t b0, uint32_t b1) {
    asm volatile(
        "mma.sync.aligned.m16n8k16.row.col.f32.f16.f16.f32 "
        "{%0,%1,%2,%3}, {%4,%5,%6,%7}, {%8,%9}, {%0,%1,%2,%3};\n"
        : "+f"(d[0]), "+f"(d[1]), "+f"(d[2]), "+f"(d[3])
        : "r"(a[0]), "r"(a[1]), "r"(a[2]), "r"(a[3]), "r"(b0), "r"(b1));
}
__device__ __forceinline__ float ex2(float x) {
    float y;
    asm("ex2.approx.f32 %0, %1;" : "=f"(y) : "f"(x));
    return y;
}
__device__ __forceinline__ uint32_t ex2h2(uint32_t x) {
    uint32_t y;
    asm("ex2.approx.f16x2 %0, %1;" : "=r"(y) : "r"(x));
    return y;
}

// ---------------- merged pre-pass: act fp16 + weight transpose/pack ----------
#define S_X 1572864u
#define ACT_BLKS 12288u

__global__ __launch_bounds__(256)
void prepack(const float* x, const float* enc, const float* qw,
             const float* pw, const float* cqw, const float* ckw,
             const float* cvw, const float* cow, const float* fcw,
             const float* fc2w,
             __half* x16, __half* enc16, uint32_t* wq, uint32_t* wp,
             uint32_t* wcq, uint32_t* wck, uint32_t* wcv, uint32_t* wco,
             uint32_t* wfc, uint32_t* wfc2)
{
    __shared__ float s[32][33];
    if (blockIdx.x < ACT_BLKS) {
        const uint32_t i = blockIdx.x * 256u + threadIdx.x;
        const float* sp; __half* d; uint32_t l;
        if (i < S_X) { sp = x;   d = x16;   l = i; }
        else         { sp = enc; d = enc16; l = i - S_X; }
        const float2 v = *(const float2*)(sp + 2 * l);
        *(__half2*)(d + 2 * l) = __floats2half2_rn(v.x, v.y);
        return;
    }
    const uint32_t t = blockIdx.x - ACT_BLKS;
    const float* src; uint32_t* dst; uint32_t K, N, lt;
    if      (t < 1728u) { src = qw;   dst = wq;   K = 768;  N = 2304; lt = t; }
    else if (t < 2304u) { src = pw;   dst = wp;   K = 768;  N = 768;  lt = t - 1728u; }
    else if (t < 2880u) { src = cqw;  dst = wcq;  K = 768;  N = 768;  lt = t - 2304u; }
    else if (t < 3456u) { src = ckw;  dst = wck;  K = 768;  N = 768;  lt = t - 2880u; }
    else if (t < 4032u) { src = cvw;  dst = wcv;  K = 768;  N = 768;  lt = t - 3456u; }
    else if (t < 4608u) { src = cow;  dst = wco;  K = 768;  N = 768;  lt = t - 4032u; }
    else if (t < 6912u) { src = fcw;  dst = wfc;  K = 768;  N = 3072; lt = t - 4608u; }
    else                { src = fc2w; dst = wfc2; K = 3072; N = 768;  lt = t - 6912u; }
    const uint32_t KT = K >> 5;
    const uint32_t k0 = (lt % KT) << 5, n0 = (lt / KT) << 5;
    const int tx = threadIdx.x & 31, ty = threadIdx.x >> 5;
    #pragma unroll
    for (int j = 0; j < 4; j++)
        s[ty + j * 8][tx] = src[(size_t)(k0 + ty + j * 8) * N + n0 + tx];
    __syncthreads();
    #pragma unroll
    for (int j = 0; j < 2; j++) {
        const int idx = threadIdx.x + j * 256;
        const int n = idx >> 4, k2 = idx & 15;
        __half2 h = __floats2half2_rn(s[2 * k2][n], s[2 * k2 + 1][n]);
        dst[(size_t)(n0 + n) * (K >> 1) + (k0 >> 1) + k2] = *(uint32_t*)&h;
    }
}

// ---------------- fp16 GEMM (MT*32)x128x64, ldmatrix, NSTG-stage cp.async ----
template<int MT, int NSTG, int EPI, int OUT>
__device__ __forceinline__
void tgemm_body(uint32_t* sm, const __half* __restrict__ Ah,
                const uint32_t* __restrict__ Bt, const float* __restrict__ bias,
                const float* __restrict__ res, float* __restrict__ Cf,
                __half* __restrict__ Ch, __half* __restrict__ Vp,
                int M, int N, int K, int mBase, int nBase)
{
    constexpr int ABUF = MT * 32 * 36;
    constexpr int STG  = ABUF + 128 * 36;

    const int tid = threadIdx.x;
    const int lane = tid & 31, warp = tid >> 5;
    const int wm = warp >> 2, wn = warp & 3;
    const int r = lane >> 2, q = lane & 3;
    const int j8 = lane >> 3, t8 = lane & 7;
    const uint32_t smemBase = (uint32_t)__cvta_generic_to_shared(sm);
    const int K2 = K >> 1;

    float acc[MT][4][4];
    #pragma unroll
    for (int mt = 0; mt < MT; mt++)
        #pragma unroll
        for (int nt = 0; nt < 4; nt++)
            #pragma unroll
            for (int e = 0; e < 4; e++) acc[mt][nt][e] = 0.f;

    const int nchunk = K >> 6;

    auto issue = [&](int c) {
        if (c < nchunk) {
            const int kc = c << 6;
            const int kc2 = c << 5;
            const uint32_t sb = smemBase + (uint32_t)((c % NSTG) * STG * 4);
            #pragma unroll
            for (int i = 0; i < MT; i++) {
                const int fid = tid + (i << 8);
                const int row = fid >> 3, k4 = (fid & 7) << 2;
                cp16(sb + (uint32_t)((row * 36 + k4) * 4),
                     Ah + (size_t)(mBase + row) * K + kc + (fid & 7) * 8);
            }
            #pragma unroll
            for (int i = 0; i < 4; i++) {
                const int fid = tid + (i << 8);
                const int row = fid >> 3, k4 = (fid & 7) << 2;
                cp16(sb + (uint32_t)((ABUF + row * 36 + k4) * 4),
                     Bt + (size_t)(nBase + row) * K2 + kc2 + (fid & 7) * 4);
            }
        }
        asm volatile("cp.async.commit_group;");
    };

    #pragma unroll
    for (int p = 0; p < NSTG - 1; p++) issue(p);

    for (int c = 0; c < nchunk; c++) {
        asm volatile("cp.async.wait_group %0;" :: "n"(NSTG - 2));
        __syncthreads();
        issue(c + NSTG - 1);

        const uint32_t smA = smemBase + (uint32_t)((c % NSTG) * STG * 4);
        const uint32_t smB = smA + (uint32_t)(ABUF * 4);
        const uint32_t aBase = smA +
            (uint32_t)(((wm * (MT * 16) + (j8 & 1) * 8 + t8) * 36 + (j8 >> 1) * 4) * 4);
        const uint32_t bBase = smB +
            (uint32_t)(((wn * 32 + (j8 >> 1) * 8 + t8) * 36 + (j8 & 1) * 4) * 4);

        #pragma unroll
        for (int ks = 0; ks < 4; ks++) {
            uint32_t af[MT][4], bq[2][4];
            #pragma unroll
            for (int mt = 0; mt < MT; mt++)
                ldsm4(af[mt], aBase + (uint32_t)((mt * 16 * 36 + ks * 8) * 4));
            #pragma unroll
            for (int p = 0; p < 2; p++)
                ldsm4(bq[p], bBase + (uint32_t)((p * 16 * 36 + ks * 8) * 4));
            #pragma unroll
            for (int mt = 0; mt < MT; mt++)
                #pragma unroll
                for (int nt = 0; nt < 4; nt++)
                    mma_f16(acc[mt][nt], af[mt],
                            bq[nt >> 1][(nt & 1) * 2], bq[nt >> 1][(nt & 1) * 2 + 1]);
        }
    }

    #pragma unroll
    for (int mt = 0; mt < MT; mt++) {
        const int row0 = mBase + wm * (MT * 16) + mt * 16 + r;
        #pragma unroll
        for (int nt = 0; nt < 4; nt++) {
            const int col = nBase + wn * 32 + nt * 8 + 2 * q;
            const float2 bv = *(const float2*)(bias + col);
            float2 v0 = make_float2(acc[mt][nt][0] + bv.x, acc[mt][nt][1] + bv.y);
            float2 v1 = make_float2(acc[mt][nt][2] + bv.x, acc[mt][nt][3] + bv.y);
            if (EPI == EPI_RELU) {
                v0.x = fmaxf(v0.x, 0.f); v0.y = fmaxf(v0.y, 0.f);
                v1.x = fmaxf(v1.x, 0.f); v1.y = fmaxf(v1.y, 0.f);
            }
            if (EPI == EPI_RES) {
                const float2 r0 = *(const float2*)(res + (size_t)row0 * N + col);
                const float2 r1 = *(const float2*)(res + (size_t)(row0 + 8) * N + col);
                v0.x += r0.x; v0.y += r0.y;
                v1.x += r1.x; v1.y += r1.y;
            }
            if (OUT == OUT_F32) {
                *(float2*)(Cf + (size_t)row0 * N + col) = v0;
                *(float2*)(Cf + (size_t)(row0 + 8) * N + col) = v1;
            }
            if (OUT == OUT_H || OUT == OUT_QKV) {
                *(__half2*)(Ch + (size_t)row0 * N + col) = __floats2half2_rn(v0.x, v0.y);
                *(__half2*)(Ch + (size_t)(row0 + 8) * N + col) = __floats2half2_rn(v1.x, v1.y);
            }
            if ((OUT == OUT_QKV && nBase >= 2 * CC) || OUT == OUT_HP) {
                const int vc = (OUT == OUT_QKV ? col - 2 * CC : col);
                const int hh = vc >> 6, dd = vc & 63;
                const int bb = row0 >> 11, t = row0 & 2047;
                __half* vb = Vp + (((size_t)(bb * HH + hh) * DD + dd) << 11) + t;
                vb[0]      = __float2half_rn(v0.x);
                vb[TT]     = __float2half_rn(v0.y);
                vb[8]      = __float2half_rn(v1.x);
                vb[TT + 8] = __float2half_rn(v1.y);
            }
        }
    }
}

template<int MT, int NSTG, int EPI, int OUT>
__global__ __launch_bounds__(256, 2)
void tgemm(const __half* __restrict__ A, const uint32_t* __restrict__ Bt,
           const float* __restrict__ bias, const float* __restrict__ res,
           float* __restrict__ Cf, __half* __restrict__ Ch,
           __half* __restrict__ Vp, int M, int N, int K)
{
    extern __shared__ uint32_t sm32[];
    tgemm_body<MT, NSTG, EPI, OUT>(sm32, A, Bt, bias, res, Cf, Ch, Vp, M, N, K,
                                   blockIdx.y * (MT * 32), blockIdx.x * 128);
}

#define GSMEM4 (3*(4*32*36 + 128*36)*4)   // 110592 B (MT=4, 3 stages)
#define GSMEM2 (3*(2*32*36 + 128*36)*4)   // 82944 B  (MT=2, 3 stages)

// ---------------- fp16 flash attention: register-P, 4-stage KV ----------------
#define TQS 36
#define TSMKV 4608
#define TSTG 4608
#define AT_SMEM ((4608 + 4*4608)*4)   // 92160 B -> 2 CTAs/SM
#define ONESF 0x3C003C00u

template<bool CAUSAL>
__global__ __launch_bounds__(256, 2)
void attn_h(const __half* __restrict__ Q, const __half* __restrict__ Kp,
            const __half* __restrict__ Vt, __half* __restrict__ O,
            int qstride, int kstride)
{
    extern __shared__ uint32_t sm32[];
    const int b = blockIdx.z, h = blockIdx.y;
    const int qt = CAUSAL ? (gridDim.x - 1 - blockIdx.x) : blockIdx.x;
    const int tid = threadIdx.x;
    const int lane = tid & 31, warp = tid >> 5;
    const int r = lane >> 2, q = lane & 3;
    const int j8 = lane >> 3, t8 = lane & 7;
    const int qbase = qt * 128;
    const int qw16 = warp * 16;
    const uint32_t smemBase = (uint32_t)__cvta_generic_to_shared(sm32);

    const int nkt = CAUSAL ? (2 * qt + 2) : (TT / 64);
    const __half* vtb = Vt + (((size_t)(b * HH + h) * DD) << 11);

    auto issueKV = [&](int kt) {
        if (kt < nkt) {
            const int kb = kt * 64;
            const uint32_t sb = smemBase + (uint32_t)((TSMKV + (kt & 3) * TSTG) * 4);
            #pragma unroll
            for (int i = 0; i < 2; i++) {
                const int lin = tid + (i << 8);
                const int row = lin >> 3, c8 = lin & 7;
                cp16(sb + (uint32_t)((row * 36 + c8 * 4) * 4),
                     Kp + (size_t)(b * TT + kb + row) * kstride + h * DD + c8 * 8);
            }
            #pragma unroll
            for (int i = 0; i < 2; i++) {
                const int lin = tid + (i << 8);
                const int row = lin >> 3, c8 = lin & 7;
                cp16(sb + (uint32_t)((2304 + row * 36 + c8 * 4) * 4),
                     vtb + ((size_t)row << 11) + kb + c8 * 8);
            }
        }
        asm volatile("cp.async.commit_group;");
    };

    issueKV(0);
    issueKV(1);
    issueKV(2);

    uint32_t* Qs = sm32;
    const __half2 hscale = __floats2half2_rn(0.125f, 0.125f);
    #pragma unroll
    for (int i = 0; i < 4; i++) {
        const int lin = tid + (i << 8);
        const int row = lin >> 3, c8 = lin & 7;
        float4 v = *(const float4*)(Q + (size_t)(b * TT + qbase + row) * qstride
                                    + h * DD + c8 * 8);
        __half2* hv = (__half2*)&v;
        #pragma unroll
        for (int e = 0; e < 4; e++) hv[e] = __hmul2(hv[e], hscale);
        *(float4*)(Qs + row * TQS + c8 * 4) = v;
    }

    const uint32_t aQ = smemBase +
        (uint32_t)(((qw16 + (j8 & 1) * 8 + t8) * TQS + (j8 >> 1) * 4) * 4);
    const uint32_t bPat =
        (uint32_t)((((j8 >> 1) * 8 + t8) * 36 + (j8 & 1) * 4) * 4);

    float oacc[8][4], lacc[4];
    float m0 = -1e30f, m1 = -1e30f;
    #pragma unroll
    for (int nt = 0; nt < 8; nt++)
        #pragma unroll
        for (int e = 0; e < 4; e++) oacc[nt][e] = 0.f;
    #pragma unroll
    for (int e = 0; e < 4; e++) lacc[e] = 0.f;

    for (int kt = 0; kt < nkt; kt++) {
        asm volatile("cp.async.wait_group 2;");
        __syncthreads();
        issueKV(kt + 3);

        const uint32_t smK = smemBase + (uint32_t)((TSMKV + (kt & 3) * TSTG) * 4);
        const uint32_t smV = smK + 2304 * 4;
        const int kbase = kt * 64;

        float sacc[8][4];
        #pragma unroll
        for (int nt = 0; nt < 8; nt++)
            #pragma unroll
            for (int e = 0; e < 4; e++) sacc[nt][e] = 0.f;

        #pragma unroll
        for (int ks = 0; ks < 4; ks++) {
            uint32_t af[4], bk[4][4];
            ldsm4(af, aQ + (uint32_t)(ks * 32));
            #pragma unroll
            for (int p = 0; p < 4; p++)
                ldsm4(bk[p], smK + bPat + (uint32_t)((p * 16 * 36 + ks * 8) * 4));
            #pragma unroll
            for (int nt = 0; nt < 8; nt++)
                mma_f16(sacc[nt], af,
                        bk[nt >> 1][(nt & 1) * 2], bk[nt >> 1][(nt & 1) * 2 + 1]);
        }

        if (CAUSAL && kbase + 63 > qbase + qw16) {
            const int row0 = qbase + qw16 + r, row1 = row0 + 8;
            #pragma unroll
            for (int nt = 0; nt < 8; nt++) {
                const int c0 = kbase + nt * 8 + 2 * q, c1 = c0 + 1;
                if (c0 > row0) sacc[nt][0] = -1e30f;
                if (c1 > row0) sacc[nt][1] = -1e30f;
                if (c0 > row1) sacc[nt][2] = -1e30f;
                if (c1 > row1) sacc[nt][3] = -1e30f;
            }
        }

        float rm0 = -1e30f, rm1 = -1e30f;
        #pragma unroll
        for (int nt = 0; nt < 8; nt++) {
            rm0 = fmaxf(rm0, fmaxf(sacc[nt][0], sacc[nt][1]));
            rm1 = fmaxf(rm1, fmaxf(sacc[nt][2], sacc[nt][3]));
        }
        rm0 = fmaxf(rm0, __shfl_xor_sync(0xffffffffu, rm0, 1));
        rm0 = fmaxf(rm0, __shfl_xor_sync(0xffffffffu, rm0, 2));
        rm1 = fmaxf(rm1, __shfl_xor_sync(0xffffffffu, rm1, 1));
        rm1 = fmaxf(rm1, __shfl_xor_sync(0xffffffffu, rm1, 2));

        const float mn0 = fmaxf(m0, rm0), mn1 = fmaxf(m1, rm1);
        const float mnl0 = mn0 * L2E, mnl1 = mn1 * L2E;
        const float cr0 = ex2(fmaf(m0, L2E, -mnl0));
        const float cr1 = ex2(fmaf(m1, L2E, -mnl1));
        m0 = mn0; m1 = mn1;

        uint32_t ph[8][2];
        #pragma unroll
        for (int nt = 0; nt < 8; nt++) {
            __half2 h0 = __floats2half2_rn(fmaf(sacc[nt][0], L2E, -mnl0),
                                           fmaf(sacc[nt][1], L2E, -mnl0));
            __half2 h1 = __floats2half2_rn(fmaf(sacc[nt][2], L2E, -mnl1),
                                           fmaf(sacc[nt][3], L2E, -mnl1));
            ph[nt][0] = ex2h2(*(uint32_t*)&h0);
            ph[nt][1] = ex2h2(*(uint32_t*)&h1);
        }

        #pragma unroll
        for (int nt = 0; nt < 8; nt++) {
            oacc[nt][0] *= cr0; oacc[nt][1] *= cr0;
            oacc[nt][2] *= cr1; oacc[nt][3] *= cr1;
        }
        lacc[0] *= cr0; lacc[1] *= cr0; lacc[2] *= cr1; lacc[3] *= cr1;

        #pragma unroll
        for (int ks = 0; ks < 4; ks++) {
            uint32_t af[4], bv[4][4];
            af[0] = ph[2 * ks][0];
            af[1] = ph[2 * ks][1];
            af[2] = ph[2 * ks + 1][0];
            af[3] = ph[2 * ks + 1][1];
            #pragma unroll
            for (int p = 0; p < 4; p++)
                ldsm4(bv[p], smV + bPat + (uint32_t)((p * 16 * 36 + ks * 8) * 4));
            #pragma unroll
            for (int nt = 0; nt < 8; nt++)
                mma_f16(oacc[nt], af,
                        bv[nt >> 1][(nt & 1) * 2], bv[nt >> 1][(nt & 1) * 2 + 1]);
            mma_f16(lacc, af, ONESF, ONESF);
        }
    }

    const float inv0 = 1.f / lacc[0], inv1 = 1.f / lacc[2];
    const int row0 = qbase + qw16 + r;
    __half* og0 = O + (size_t)(b * TT + row0) * CC + h * DD + 2 * q;
    __half* og1 = O + (size_t)(b * TT + row0 + 8) * CC + h * DD + 2 * q;
    #pragma unroll
    for (int nt = 0; nt < 8; nt++) {
        *(__half2*)(og0 + nt * 8) = __floats2half2_rn(oacc[nt][0] * inv0,
                                                      oacc[nt][1] * inv0);
        *(__half2*)(og1 + nt * 8) = __floats2half2_rn(oacc[nt][2] * inv1,
                                                      oacc[nt][3] * inv1);
    }
}

// ---------------- LayerNorm ---------------------------------------------------
__global__ __launch_bounds__(256)
void layernorm_k(const float* __restrict__ in, const float* __restrict__ g,
                 const float* __restrict__ b, float* __restrict__ out,
                 __half* __restrict__ outh)
{
    const int row = blockIdx.x;
    const int tid = threadIdx.x;
    const float* x = in + (size_t)row * CC;

    const float v0 = x[tid], v1 = x[tid + 256], v2 = x[tid + 512];
    float s = v0 + v1 + v2;
    float sq = v0 * v0 + v1 * v1 + v2 * v2;

    #pragma unroll
    for (int off = 16; off; off >>= 1) {
        s  += __shfl_xor_sync(0xffffffffu, s, off);
        sq += __shfl_xor_sync(0xffffffffu, sq, off);
    }
    __shared__ float red[16];
    const int wid = tid >> 5, lane = tid & 31;
    if (lane == 0) { red[wid] = s; red[wid + 8] = sq; }
    __syncthreads();

    float ts = 0.f, tq = 0.f;
    #pragma unroll
    for (int i = 0; i < 8; i++) { ts += red[i]; tq += red[i + 8]; }

    const float mu = ts * (1.f / CC);
    const float var = tq * (1.f / CC) - mu * mu;
    const float rstd = rsqrtf(var + 1e-5f);

    const float y0 = (v0 - mu) * rstd * g[tid]       + b[tid];
    const float y1 = (v1 - mu) * rstd * g[tid + 256] + b[tid + 256];
    const float y2 = (v2 - mu) * rstd * g[tid + 512] + b[tid + 512];

    float* orow = out + (size_t)row * CC;
    orow[tid] = y0; orow[tid + 256] = y1; orow[tid + 512] = y2;
    if (outh) {
        __half* hrow = outh + (size_t)row * CC;
        hrow[tid]       = __float2half_rn(y0);
        hrow[tid + 256] = __float2half_rn(y1);
        hrow[tid + 512] = __float2half_rn(y2);
    }
}

// ---------------- launch ------------------------------------------------------
extern "C" void kernel_launch(void* const* d_in, const int* in_sizes, int n_in,
                              void* d_out, int out_size)
{
    const float* x      = (const float*)d_in[0];
    const float* enc    = (const float*)d_in[1];
    const float* ln1_g  = (const float*)d_in[2];
    const float* ln1_b  = (const float*)d_in[3];
    const float* qkv_w  = (const float*)d_in[4];
    const float* qkv_b  = (const float*)d_in[5];
    const float* proj_w = (const float*)d_in[6];
    const float* proj_b = (const float*)d_in[7];
    const float* ln2_g  = (const float*)d_in[8];
    const float* ln2_b  = (const float*)d_in[9];
    const float* caq_w  = (const float*)d_in[10];
    const float* caq_b  = (const float*)d_in[11];
    const float* cak_w  = (const float*)d_in[12];
    const float* cak_b  = (const float*)d_in[13];
    const float* cav_w  = (const float*)d_in[14];
    const float* cav_b  = (const float*)d_in[15];
    const float* cao_w  = (const float*)d_in[16];
    const float* cao_b  = (const float*)d_in[17];
    const float* ln3_g  = (const float*)d_in[18];
    const float* ln3_b  = (const float*)d_in[19];
    const float* fc_w   = (const float*)d_in[20];
    const float* fc_b   = (const float*)d_in[21];
    const float* fc2_w  = (const float*)d_in[22];
    const float* fc2_b  = (const float*)d_in[23];
    float* out = (float*)d_out;

    float *res, *x1, *x2;
    __half *x16, *enc16, *qkv16, *vt, *att16, *x1r, *x2r, *cq16, *ck16, *cvt, *h16;
    uint32_t *wq, *wp, *wcq, *wck, *wcv, *wco, *wfc, *wfc2;
    cudaGetSymbolAddress((void**)&res,   g_res);
    cudaGetSymbolAddress((void**)&x1,    g_x1);
    cudaGetSymbolAddress((void**)&x2,    g_x2);
    cudaGetSymbolAddress((void**)&x16,   g_x16);
    cudaGetSymbolAddress((void**)&enc16, g_enc16);
    cudaGetSymbolAddress((void**)&qkv16, g_qkv16);
    cudaGetSymbolAddress((void**)&vt,    g_vt);
    cudaGetSymbolAddress((void**)&att16, g_att16);
    cudaGetSymbolAddress((void**)&x1r,   g_x1r);
    cudaGetSymbolAddress((void**)&x2r,   g_x2r);
    cudaGetSymbolAddress((void**)&cq16,  g_cq16);
    cudaGetSymbolAddress((void**)&ck16,  g_ck16);
    cudaGetSymbolAddress((void**)&cvt,   g_cvt);
    cudaGetSymbolAddress((void**)&h16,   g_h16);
    cudaGetSymbolAddress((void**)&wq,    g_wq);
    cudaGetSymbolAddress((void**)&wp,    g_wp);
    cudaGetSymbolAddress((void**)&wcq,   g_wcq);
    cudaGetSymbolAddress((void**)&wck,   g_wck);
    cudaGetSymbolAddress((void**)&wcv,   g_wcv);
    cudaGetSymbolAddress((void**)&wco,   g_wco);
    cudaGetSymbolAddress((void**)&wfc,   g_wfc);
    cudaGetSymbolAddress((void**)&wfc2,  g_wfc2);

    // one-time stream/event creation (no device memory involved; identical
    // captured work on every call)
    static cudaStream_t s2 = nullptr;
    static cudaEvent_t evFork = nullptr, evJoin = nullptr;
    if (s2 == nullptr) {
        cudaStreamCreateWithFlags(&s2, cudaStreamNonBlocking);
        cudaEventCreateWithFlags(&evFork, cudaEventDisableTiming);
        cudaEventCreateWithFlags(&evJoin, cudaEventDisableTiming);
    }

    cudaFuncSetAttribute(attn_h<true>,
                         cudaFuncAttributeMaxDynamicSharedMemorySize, AT_SMEM);
    cudaFuncSetAttribute(attn_h<false>,
                         cudaFuncAttributeMaxDynamicSharedMemorySize, AT_SMEM);
    cudaFuncSetAttribute((const void*)tgemm<4, 3, EPI_NONE, OUT_QKV>,
                         cudaFuncAttributeMaxDynamicSharedMemorySize, GSMEM4);
    cudaFuncSetAttribute((const void*)tgemm<4, 3, EPI_RELU, OUT_H>,
                         cudaFuncAttributeMaxDynamicSharedMemorySize, GSMEM4);
    cudaFuncSetAttribute((const void*)tgemm<4, 3, EPI_NONE, OUT_H>,
                         cudaFuncAttributeMaxDynamicSharedMemorySize, GSMEM4);
    cudaFuncSetAttribute((const void*)tgemm<4, 3, EPI_NONE, OUT_HP>,
                         cudaFuncAttributeMaxDynamicSharedMemorySize, GSMEM4);
    cudaFuncSetAttribute((const void*)tgemm<2, 3, EPI_RES, OUT_F32>,
                         cudaFuncAttributeMaxDynamicSharedMemorySize, GSMEM2);

    const dim3 thr(256);
    const dim3 gqkv(3 * CC / 128, MROWS / 128);      // (18,32)
    const dim3 g768m4(CC / 128, MROWS / 128);        // (6,32) MT=4
    const dim3 g768s(CC / 128, MROWS / 64);          // (6,64) MT=2
    const dim3 gfc(4 * CC / 128, MROWS / 128);       // (24,32)
    const dim3 gattn(TT / 128, HH, BB);              // (16,12,2)

    // 0) merged pre-pass (main stream)
    prepack<<<ACT_BLKS + 9216, thr>>>(x, enc, qkv_w, proj_w, caq_w, cak_w,
                                      cav_w, cao_w, fc_w, fc2_w,
                                      x16, enc16, wq, wp, wcq, wck, wcv, wco,
                                      wfc, wfc2);

    // fork: ck / cv projections depend only on prepack -> side stream
    cudaEventRecord(evFork, 0);
    cudaStreamWaitEvent(s2, evFork, 0);
    tgemm<4, 3, EPI_NONE, OUT_H><<<g768m4, thr, GSMEM4, s2>>>(
        enc16, wck, cak_b, nullptr, nullptr, ck16, nullptr, MROWS, CC, CC);
    tgemm<4, 3, EPI_NONE, OUT_HP><<<g768m4, thr, GSMEM4, s2>>>(
        enc16, wcv, cav_b, nullptr, nullptr, nullptr, cvt, MROWS, CC, CC);
    cudaEventRecord(evJoin, s2);

    // main stream: self-attention block
    tgemm<4, 3, EPI_NONE, OUT_QKV><<<gqkv, thr, GSMEM4>>>(x16, wq, qkv_b,
                                                          nullptr, nullptr,
                                                          qkv16, vt,
                                                          MROWS, 3 * CC, CC);
    attn_h<true><<<gattn, thr, AT_SMEM>>>(qkv16, qkv16 + CC, vt, att16,
                                          3 * CC, 3 * CC);
    tgemm<2, 3, EPI_RES, OUT_F32><<<g768s, thr, GSMEM2>>>(att16, wp, proj_b,
                                                          x, res, nullptr,
                                                          nullptr, MROWS, CC, CC);
    layernorm_k<<<MROWS, thr>>>(res, ln1_g, ln1_b, x1, x1r);

    // cq projection (needs x1r)
    tgemm<4, 3, EPI_NONE, OUT_H><<<g768m4, thr, GSMEM4>>>(
        x1r, wcq, caq_b, nullptr, nullptr, cq16, nullptr, MROWS, CC, CC);

    // join: cross-attention needs ck/cv from side stream
    cudaStreamWaitEvent(0, evJoin, 0);
    attn_h<false><<<gattn, thr, AT_SMEM>>>(cq16, ck16, cvt, att16, CC, CC);
    tgemm<2, 3, EPI_RES, OUT_F32><<<g768s, thr, GSMEM2>>>(att16, wco, cao_b,
                                                          x1, res, nullptr,
                                                          nullptr, MROWS, CC, CC);
    layernorm_k<<<MROWS, thr>>>(res, ln2_g, ln2_b, x2, x2r);

    // MLP
    tgemm<4, 3, EPI_RELU, OUT_H><<<gfc, thr, GSMEM4>>>(x2r, wfc, fc_b, nullptr,
                                                       nullptr, h16, nullptr,
                                                       MROWS, 4 * CC, CC);
    tgemm<2, 3, EPI_RES, OUT_F32><<<g768s, thr, GSMEM2>>>(h16, wfc2, fc2_b,
                                                          x2, res, nullptr,
                                                          nullptr, MROWS, CC,
                                                          4 * CC);
    layernorm_k<<<MROWS, thr>>>(res, ln3_g, ln3_b, out, nullptr);
}

// round 16
// speedup vs baseline: 1.0135x; 1.0135x over previous
#include <cuda_runtime.h>
#include <cuda_fp16.h>
#include <math.h>
#include <stdint.h>

#define BB 2
#define TT 2048
#define CC 768
#define HH 12
#define DD 64
#define MROWS (BB*TT)   // 4096
#define L2E 1.4426950408889634f

// ---------------- scratch ----------------------------------------------------
__device__ float g_res[(size_t)MROWS * CC];
__device__ float g_x1 [(size_t)MROWS * CC];
__device__ float g_x2 [(size_t)MROWS * CC];
__device__ __half g_x16  [(size_t)MROWS * CC];
__device__ __half g_enc16[(size_t)MROWS * CC];
__device__ __half g_qkv16[(size_t)MROWS * 3 * CC];
__device__ __half g_vt   [(size_t)BB * HH * DD * TT];   // V transposed [b][h][d][t]
__device__ __half g_att16[(size_t)MROWS * CC];
__device__ __half g_x1r  [(size_t)MROWS * CC];
__device__ __half g_x2r  [(size_t)MROWS * CC];
__device__ __half g_cq16 [(size_t)MROWS * CC];
__device__ __half g_ck16 [(size_t)MROWS * CC];
__device__ __half g_cvt  [(size_t)BB * HH * DD * TT];   // cross V transposed
__device__ __half g_h16  [(size_t)MROWS * 4 * CC];
// fp16 weights TRANSPOSED to [N][K], k-pair-packed as u32 [N][K/2]
__device__ uint32_t g_wq  [(size_t)3*CC * CC/2];
__device__ uint32_t g_wp  [(size_t)CC * CC/2];
__device__ uint32_t g_wcq [(size_t)CC * CC/2];
__device__ uint32_t g_wck [(size_t)CC * CC/2];
__device__ uint32_t g_wcv [(size_t)CC * CC/2];
__device__ uint32_t g_wco [(size_t)CC * CC/2];
__device__ uint32_t g_wfc [(size_t)4*CC * CC/2];
__device__ uint32_t g_wfc2[(size_t)CC * 4*CC/2];

enum { EPI_NONE = 0, EPI_RELU = 1, EPI_RES = 2 };
enum { OUT_F32 = 0, OUT_H = 1, OUT_QKV = 2, OUT_HP = 3 };

__device__ __forceinline__ void cp16(uint32_t s, const void* g) {
    asm volatile("cp.async.cg.shared.global [%0], [%1], 16;" :: "r"(s), "l"(g));
}
__device__ __forceinline__ void ldsm4(uint32_t* d, uint32_t addr) {
    asm volatile("ldmatrix.sync.aligned.m8n8.x4.shared.b16 {%0,%1,%2,%3}, [%4];"
        : "=r"(d[0]), "=r"(d[1]), "=r"(d[2]), "=r"(d[3]) : "r"(addr));
}
__device__ __forceinline__ void mma_f16(float* d, const uint32_t* a,
                                        uint32_t b0, uint32_t b1) {
    asm volatile(
        "mma.sync.aligned.m16n8k16.row.col.f32.f16.f16.f32 "
        "{%0,%1,%2,%3}, {%4,%5,%6,%7}, {%8,%9}, {%0,%1,%2,%3};\n"
        : "+f"(d[0]), "+f"(d[1]), "+f"(d[2]), "+f"(d[3])
        : "r"(a[0]), "r"(a[1]), "r"(a[2]), "r"(a[3]), "r"(b0), "r"(b1));
}
__device__ __forceinline__ float ex2(float x) {
    float y;
    asm("ex2.approx.f32 %0, %1;" : "=f"(y) : "f"(x));
    return y;
}
__device__ __forceinline__ uint32_t ex2h2(uint32_t x) {
    uint32_t y;
    asm("ex2.approx.f16x2 %0, %1;" : "=r"(y) : "r"(x));
    return y;
}

// ---------------- merged pre-pass: act fp16 + weight transpose/pack ----------
#define S_X 1572864u
#define ACT_BLKS 12288u

__global__ __launch_bounds__(256)
void prepack(const float* x, const float* enc, const float* qw,
             const float* pw, const float* cqw, const float* ckw,
             const float* cvw, const float* cow, const float* fcw,
             const float* fc2w,
             __half* x16, __half* enc16, uint32_t* wq, uint32_t* wp,
             uint32_t* wcq, uint32_t* wck, uint32_t* wcv, uint32_t* wco,
             uint32_t* wfc, uint32_t* wfc2)
{
    __shared__ float s[32][33];
    if (blockIdx.x < ACT_BLKS) {
        const uint32_t i = blockIdx.x * 256u + threadIdx.x;
        const float* sp; __half* d; uint32_t l;
        if (i < S_X) { sp = x;   d = x16;   l = i; }
        else         { sp = enc; d = enc16; l = i - S_X; }
        const float2 v = *(const float2*)(sp + 2 * l);
        *(__half2*)(d + 2 * l) = __floats2half2_rn(v.x, v.y);
        return;
    }
    const uint32_t t = blockIdx.x - ACT_BLKS;
    const float* src; uint32_t* dst; uint32_t K, N, lt;
    if      (t < 1728u) { src = qw;   dst = wq;   K = 768;  N = 2304; lt = t; }
    else if (t < 2304u) { src = pw;   dst = wp;   K = 768;  N = 768;  lt = t - 1728u; }
    else if (t < 2880u) { src = cqw;  dst = wcq;  K = 768;  N = 768;  lt = t - 2304u; }
    else if (t < 3456u) { src = ckw;  dst = wck;  K = 768;  N = 768;  lt = t - 2880u; }
    else if (t < 4032u) { src = cvw;  dst = wcv;  K = 768;  N = 768;  lt = t - 3456u; }
    else if (t < 4608u) { src = cow;  dst = wco;  K = 768;  N = 768;  lt = t - 4032u; }
    else if (t < 6912u) { src = fcw;  dst = wfc;  K = 768;  N = 3072; lt = t - 4608u; }
    else                { src = fc2w; dst = wfc2; K = 3072; N = 768;  lt = t - 6912u; }
    const uint32_t KT = K >> 5;
    const uint32_t k0 = (lt % KT) << 5, n0 = (lt / KT) << 5;
    const int tx = threadIdx.x & 31, ty = threadIdx.x >> 5;
    #pragma unroll
    for (int j = 0; j < 4; j++)
        s[ty + j * 8][tx] = src[(size_t)(k0 + ty + j * 8) * N + n0 + tx];
    __syncthreads();
    #pragma unroll
    for (int j = 0; j < 2; j++) {
        const int idx = threadIdx.x + j * 256;
        const int n = idx >> 4, k2 = idx & 15;
        __half2 h = __floats2half2_rn(s[2 * k2][n], s[2 * k2 + 1][n]);
        dst[(size_t)(n0 + n) * (K >> 1) + (k0 >> 1) + k2] = *(uint32_t*)&h;
    }
}

// ---------------- fp16 GEMM (MT*32)x128x64, ldmatrix, 3-stage cp.async -------
template<int MT, int EPI, int OUT>
__device__ __forceinline__
void tgemm_body(uint32_t* sm, const __half* __restrict__ Ah,
                const uint32_t* __restrict__ Bt, const float* __restrict__ bias,
                const float* __restrict__ res, float* __restrict__ Cf,
                __half* __restrict__ Ch, __half* __restrict__ Vp,
                int M, int N, int K, int mBase, int nBase)
{
    constexpr int ABUF = MT * 32 * 36;
    constexpr int STG  = ABUF + 128 * 36;

    const int tid = threadIdx.x;
    const int lane = tid & 31, warp = tid >> 5;
    const int wm = warp >> 2, wn = warp & 3;
    const int r = lane >> 2, q = lane & 3;
    const int j8 = lane >> 3, t8 = lane & 7;
    const uint32_t smemBase = (uint32_t)__cvta_generic_to_shared(sm);
    const int K2 = K >> 1;

    float acc[MT][4][4];
    #pragma unroll
    for (int mt = 0; mt < MT; mt++)
        #pragma unroll
        for (int nt = 0; nt < 4; nt++)
            #pragma unroll
            for (int e = 0; e < 4; e++) acc[mt][nt][e] = 0.f;

    const int nchunk = K >> 6;

    auto issue = [&](int c) {
        if (c < nchunk) {
            const int kc = c << 6;
            const int kc2 = c << 5;
            const uint32_t sb = smemBase + (uint32_t)((c % 3) * STG * 4);
            #pragma unroll
            for (int i = 0; i < MT; i++) {
                const int fid = tid + (i << 8);
                const int row = fid >> 3, k4 = (fid & 7) << 2;
                cp16(sb + (uint32_t)((row * 36 + k4) * 4),
                     Ah + (size_t)(mBase + row) * K + kc + (fid & 7) * 8);
            }
            #pragma unroll
            for (int i = 0; i < 4; i++) {
                const int fid = tid + (i << 8);
                const int row = fid >> 3, k4 = (fid & 7) << 2;
                cp16(sb + (uint32_t)((ABUF + row * 36 + k4) * 4),
                     Bt + (size_t)(nBase + row) * K2 + kc2 + (fid & 7) * 4);
            }
        }
        asm volatile("cp.async.commit_group;");
    };

    issue(0);
    issue(1);

    for (int c = 0; c < nchunk; c++) {
        asm volatile("cp.async.wait_group 1;");
        __syncthreads();
        issue(c + 2);

        const uint32_t smA = smemBase + (uint32_t)((c % 3) * STG * 4);
        const uint32_t smB = smA + (uint32_t)(ABUF * 4);
        const uint32_t aBase = smA +
            (uint32_t)(((wm * (MT * 16) + (j8 & 1) * 8 + t8) * 36 + (j8 >> 1) * 4) * 4);
        const uint32_t bBase = smB +
            (uint32_t)(((wn * 32 + (j8 >> 1) * 8 + t8) * 36 + (j8 & 1) * 4) * 4);

        #pragma unroll
        for (int ks = 0; ks < 4; ks++) {
            uint32_t af[MT][4], bq[2][4];
            #pragma unroll
            for (int mt = 0; mt < MT; mt++)
                ldsm4(af[mt], aBase + (uint32_t)((mt * 16 * 36 + ks * 8) * 4));
            #pragma unroll
            for (int p = 0; p < 2; p++)
                ldsm4(bq[p], bBase + (uint32_t)((p * 16 * 36 + ks * 8) * 4));
            #pragma unroll
            for (int mt = 0; mt < MT; mt++)
                #pragma unroll
                for (int nt = 0; nt < 4; nt++)
                    mma_f16(acc[mt][nt], af[mt],
                            bq[nt >> 1][(nt & 1) * 2], bq[nt >> 1][(nt & 1) * 2 + 1]);
        }
    }

    #pragma unroll
    for (int mt = 0; mt < MT; mt++) {
        const int row0 = mBase + wm * (MT * 16) + mt * 16 + r;
        #pragma unroll
        for (int nt = 0; nt < 4; nt++) {
            const int col = nBase + wn * 32 + nt * 8 + 2 * q;
            const float2 bv = *(const float2*)(bias + col);
            float2 v0 = make_float2(acc[mt][nt][0] + bv.x, acc[mt][nt][1] + bv.y);
            float2 v1 = make_float2(acc[mt][nt][2] + bv.x, acc[mt][nt][3] + bv.y);
            if (EPI == EPI_RELU) {
                v0.x = fmaxf(v0.x, 0.f); v0.y = fmaxf(v0.y, 0.f);
                v1.x = fmaxf(v1.x, 0.f); v1.y = fmaxf(v1.y, 0.f);
            }
            if (EPI == EPI_RES) {
                const float2 r0 = *(const float2*)(res + (size_t)row0 * N + col);
                const float2 r1 = *(const float2*)(res + (size_t)(row0 + 8) * N + col);
                v0.x += r0.x; v0.y += r0.y;
                v1.x += r1.x; v1.y += r1.y;
            }
            if (OUT == OUT_F32) {
                *(float2*)(Cf + (size_t)row0 * N + col) = v0;
                *(float2*)(Cf + (size_t)(row0 + 8) * N + col) = v1;
            }
            if (OUT == OUT_H || OUT == OUT_QKV) {
                *(__half2*)(Ch + (size_t)row0 * N + col) = __floats2half2_rn(v0.x, v0.y);
                *(__half2*)(Ch + (size_t)(row0 + 8) * N + col) = __floats2half2_rn(v1.x, v1.y);
            }
            if ((OUT == OUT_QKV && nBase >= 2 * CC) || OUT == OUT_HP) {
                const int vc = (OUT == OUT_QKV ? col - 2 * CC : col);
                const int hh = vc >> 6, dd = vc & 63;
                const int bb = row0 >> 11, t = row0 & 2047;
                __half* vb = Vp + (((size_t)(bb * HH + hh) * DD + dd) << 11) + t;
                vb[0]      = __float2half_rn(v0.x);
                vb[TT]     = __float2half_rn(v0.y);
                vb[8]      = __float2half_rn(v1.x);
                vb[TT + 8] = __float2half_rn(v1.y);
            }
        }
    }
}

template<int MT, int EPI, int OUT>
__global__ __launch_bounds__(256, 2)
void tgemm(const __half* __restrict__ A, const uint32_t* __restrict__ Bt,
           const float* __restrict__ bias, const float* __restrict__ res,
           float* __restrict__ Cf, __half* __restrict__ Ch,
           __half* __restrict__ Vp, int M, int N, int K)
{
    extern __shared__ uint32_t sm32[];
    tgemm_body<MT, EPI, OUT>(sm32, A, Bt, bias, res, Cf, Ch, Vp, M, N, K,
                             blockIdx.y * (MT * 32), blockIdx.x * 128);
}

__global__ __launch_bounds__(256, 2)
void tgemm3(const __half* __restrict__ x1r, const __half* __restrict__ encr,
            const uint32_t* qw, const float* qb,
            const uint32_t* kw, const float* kb,
            const uint32_t* vw, const float* vb,
            __half* cq, __half* ck, __half* cvt)
{
    extern __shared__ uint32_t sm32[];
    const int z = blockIdx.z;
    const int mB = blockIdx.y * 128, nB = blockIdx.x * 128;
    if (z == 0)
        tgemm_body<4, EPI_NONE, OUT_H>(sm32, x1r, qw, qb, nullptr, nullptr, cq,
                                       nullptr, MROWS, CC, CC, mB, nB);
    else if (z == 1)
        tgemm_body<4, EPI_NONE, OUT_H>(sm32, encr, kw, kb, nullptr, nullptr, ck,
                                       nullptr, MROWS, CC, CC, mB, nB);
    else
        tgemm_body<4, EPI_NONE, OUT_HP>(sm32, encr, vw, vb, nullptr, nullptr,
                                        nullptr, cvt, MROWS, CC, CC, mB, nB);
}

#define GSMEM4 (3*(4*32*36 + 128*36)*4)   // 110592 B
#define GSMEM2 (3*(2*32*36 + 128*36)*4)   // 82944 B

// ---------------- fp16 flash attention: 64q tiles, 128 thr, 3 CTAs/SM --------
// SMEM u32: Qs[64][36] @0 (2304), KV stages @2304: K[64][36]+V[64][36] per
// stage (4608 u32), 3 stages. Total 16128 u32 = 64512 B -> 3 CTAs/SM.
#define TQS 36
#define A_TSMKV 2304
#define A_TSTG 4608
#define AT_SMEM (16128*4)
#define ONESF 0x3C003C00u

template<bool CAUSAL>
__global__ __launch_bounds__(128, 3)
void attn_h(const __half* __restrict__ Q, const __half* __restrict__ Kp,
            const __half* __restrict__ Vt, __half* __restrict__ O,
            int qstride, int kstride)
{
    extern __shared__ uint32_t sm32[];
    const int b = blockIdx.z, h = blockIdx.y;
    const int qt = CAUSAL ? (gridDim.x - 1 - blockIdx.x) : blockIdx.x;
    const int tid = threadIdx.x;
    const int lane = tid & 31, warp = tid >> 5;       // 4 warps
    const int r = lane >> 2, q = lane & 3;
    const int j8 = lane >> 3, t8 = lane & 7;
    const int qbase = qt * 64;
    const int qw16 = warp * 16;
    const uint32_t smemBase = (uint32_t)__cvta_generic_to_shared(sm32);

    const int nkt = CAUSAL ? (qt + 1) : (TT / 64);
    const __half* vtb = Vt + (((size_t)(b * HH + h) * DD) << 11);

    auto issueKV = [&](int kt) {
        if (kt < nkt) {
            const int kb = kt * 64;
            const uint32_t sb = smemBase + (uint32_t)((A_TSMKV + (kt % 3) * A_TSTG) * 4);
            #pragma unroll
            for (int i = 0; i < 4; i++) {            // K: 512 cp16
                const int lin = tid + (i << 7);
                const int row = lin >> 3, c8 = lin & 7;
                cp16(sb + (uint32_t)((row * 36 + c8 * 4) * 4),
                     Kp + (size_t)(b * TT + kb + row) * kstride + h * DD + c8 * 8);
            }
            #pragma unroll
            for (int i = 0; i < 4; i++) {            // V: 512 cp16
                const int lin = tid + (i << 7);
                const int row = lin >> 3, c8 = lin & 7;
                cp16(sb + (uint32_t)((2304 + row * 36 + c8 * 4) * 4),
                     vtb + ((size_t)row << 11) + kb + c8 * 8);
            }
        }
        asm volatile("cp.async.commit_group;");
    };

    issueKV(0);
    issueKV(1);

    // Q tile: 64 rows (scaled by 0.125, exact)
    uint32_t* Qs = sm32;
    const __half2 hscale = __floats2half2_rn(0.125f, 0.125f);
    #pragma unroll
    for (int i = 0; i < 4; i++) {
        const int lin = tid + (i << 7);
        const int row = lin >> 3, c8 = lin & 7;
        float4 v = *(const float4*)(Q + (size_t)(b * TT + qbase + row) * qstride
                                    + h * DD + c8 * 8);
        __half2* hv = (__half2*)&v;
        #pragma unroll
        for (int e = 0; e < 4; e++) hv[e] = __hmul2(hv[e], hscale);
        *(float4*)(Qs + row * TQS + c8 * 4) = v;
    }

    const uint32_t aQ = smemBase +
        (uint32_t)(((qw16 + (j8 & 1) * 8 + t8) * TQS + (j8 >> 1) * 4) * 4);
    const uint32_t bPat =
        (uint32_t)((((j8 >> 1) * 8 + t8) * 36 + (j8 & 1) * 4) * 4);

    float oacc[8][4], lacc[4];
    float m0 = -1e30f, m1 = -1e30f;
    #pragma unroll
    for (int nt = 0; nt < 8; nt++)
        #pragma unroll
        for (int e = 0; e < 4; e++) oacc[nt][e] = 0.f;
    #pragma unroll
    for (int e = 0; e < 4; e++) lacc[e] = 0.f;

    for (int kt = 0; kt < nkt; kt++) {
        asm volatile("cp.async.wait_group 1;");
        __syncthreads();
        issueKV(kt + 2);

        const uint32_t smK = smemBase + (uint32_t)((A_TSMKV + (kt % 3) * A_TSTG) * 4);
        const uint32_t smV = smK + 2304 * 4;
        const int kbase = kt * 64;

        float sacc[8][4];
        #pragma unroll
        for (int nt = 0; nt < 8; nt++)
            #pragma unroll
            for (int e = 0; e < 4; e++) sacc[nt][e] = 0.f;

        #pragma unroll
        for (int ks = 0; ks < 4; ks++) {
            uint32_t af[4], bk[4][4];
            ldsm4(af, aQ + (uint32_t)(ks * 32));
            #pragma unroll
            for (int p = 0; p < 4; p++)
                ldsm4(bk[p], smK + bPat + (uint32_t)((p * 16 * 36 + ks * 8) * 4));
            #pragma unroll
            for (int nt = 0; nt < 8; nt++)
                mma_f16(sacc[nt], af,
                        bk[nt >> 1][(nt & 1) * 2], bk[nt >> 1][(nt & 1) * 2 + 1]);
        }

        if (CAUSAL && kbase + 63 > qbase + qw16) {
            const int row0 = qbase + qw16 + r, row1 = row0 + 8;
            #pragma unroll
            for (int nt = 0; nt < 8; nt++) {
                const int c0 = kbase + nt * 8 + 2 * q, c1 = c0 + 1;
                if (c0 > row0) sacc[nt][0] = -1e30f;
                if (c1 > row0) sacc[nt][1] = -1e30f;
                if (c0 > row1) sacc[nt][2] = -1e30f;
                if (c1 > row1) sacc[nt][3] = -1e30f;
            }
        }

        float rm0 = -1e30f, rm1 = -1e30f;
        #pragma unroll
        for (int nt = 0; nt < 8; nt++) {
            rm0 = fmaxf(rm0, fmaxf(sacc[nt][0], sacc[nt][1]));
            rm1 = fmaxf(rm1, fmaxf(sacc[nt][2], sacc[nt][3]));
        }
        rm0 = fmaxf(rm0, __shfl_xor_sync(0xffffffffu, rm0, 1));
        rm0 = fmaxf(rm0, __shfl_xor_sync(0xffffffffu, rm0, 2));
        rm1 = fmaxf(rm1, __shfl_xor_sync(0xffffffffu, rm1, 1));
        rm1 = fmaxf(rm1, __shfl_xor_sync(0xffffffffu, rm1, 2));

        const float mn0 = fmaxf(m0, rm0), mn1 = fmaxf(m1, rm1);
        const float mnl0 = mn0 * L2E, mnl1 = mn1 * L2E;
        const float cr0 = ex2(fmaf(m0, L2E, -mnl0));
        const float cr1 = ex2(fmaf(m1, L2E, -mnl1));
        m0 = mn0; m1 = mn1;

        uint32_t ph[8][2];
        #pragma unroll
        for (int nt = 0; nt < 8; nt++) {
            __half2 h0 = __floats2half2_rn(fmaf(sacc[nt][0], L2E, -mnl0),
                                           fmaf(sacc[nt][1], L2E, -mnl0));
            __half2 h1 = __floats2half2_rn(fmaf(sacc[nt][2], L2E, -mnl1),
                                           fmaf(sacc[nt][3], L2E, -mnl1));
            ph[nt][0] = ex2h2(*(uint32_t*)&h0);
            ph[nt][1] = ex2h2(*(uint32_t*)&h1);
        }

        #pragma unroll
        for (int nt = 0; nt < 8; nt++) {
            oacc[nt][0] *= cr0; oacc[nt][1] *= cr0;
            oacc[nt][2] *= cr1; oacc[nt][3] *= cr1;
        }
        lacc[0] *= cr0; lacc[1] *= cr0; lacc[2] *= cr1; lacc[3] *= cr1;

        #pragma unroll
        for (int ks = 0; ks < 4; ks++) {
            uint32_t af[4], bv[4][4];
            af[0] = ph[2 * ks][0];
            af[1] = ph[2 * ks][1];
            af[2] = ph[2 * ks + 1][0];
            af[3] = ph[2 * ks + 1][1];
            #pragma unroll
            for (int p = 0; p < 4; p++)
                ldsm4(bv[p], smV + bPat + (uint32_t)((p * 16 * 36 + ks * 8) * 4));
            #pragma unroll
            for (int nt = 0; nt < 8; nt++)
                mma_f16(oacc[nt], af,
                        bv[nt >> 1][(nt & 1) * 2], bv[nt >> 1][(nt & 1) * 2 + 1]);
            mma_f16(lacc, af, ONESF, ONESF);
        }
    }

    const float inv0 = 1.f / lacc[0], inv1 = 1.f / lacc[2];
    const int row0 = qbase + qw16 + r;
    __half* og0 = O + (size_t)(b * TT + row0) * CC + h * DD + 2 * q;
    __half* og1 = O + (size_t)(b * TT + row0 + 8) * CC + h * DD + 2 * q;
    #pragma unroll
    for (int nt = 0; nt < 8; nt++) {
        *(__half2*)(og0 + nt * 8) = __floats2half2_rn(oacc[nt][0] * inv0,
                                                      oacc[nt][1] * inv0);
        *(__half2*)(og1 + nt * 8) = __floats2half2_rn(oacc[nt][2] * inv1,
                                                      oacc[nt][3] * inv1);
    }
}

// ---------------- LayerNorm ---------------------------------------------------
__global__ __launch_bounds__(256)
void layernorm_k(const float* __restrict__ in, const float* __restrict__ g,
                 const float* __restrict__ b, float* __restrict__ out,
                 __half* __restrict__ outh)
{
    const int row = blockIdx.x;
    const int tid = threadIdx.x;
    const float* x = in + (size_t)row * CC;

    const float v0 = x[tid], v1 = x[tid + 256], v2 = x[tid + 512];
    float s = v0 + v1 + v2;
    float sq = v0 * v0 + v1 * v1 + v2 * v2;

    #pragma unroll
    for (int off = 16; off; off >>= 1) {
        s  += __shfl_xor_sync(0xffffffffu, s, off);
        sq += __shfl_xor_sync(0xffffffffu, sq, off);
    }
    __shared__ float red[16];
    const int wid = tid >> 5, lane = tid & 31;
    if (lane == 0) { red[wid] = s; red[wid + 8] = sq; }
    __syncthreads();

    float ts = 0.f, tq = 0.f;
    #pragma unroll
    for (int i = 0; i < 8; i++) { ts += red[i]; tq += red[i + 8]; }

    const float mu = ts * (1.f / CC);
    const float var = tq * (1.f / CC) - mu * mu;
    const float rstd = rsqrtf(var + 1e-5f);

    const float y0 = (v0 - mu) * rstd * g[tid]       + b[tid];
    const float y1 = (v1 - mu) * rstd * g[tid + 256] + b[tid + 256];
    const float y2 = (v2 - mu) * rstd * g[tid + 512] + b[tid + 512];

    float* orow = out + (size_t)row * CC;
    orow[tid] = y0; orow[tid + 256] = y1; orow[tid + 512] = y2;
    if (outh) {
        __half* hrow = outh + (size_t)row * CC;
        hrow[tid]       = __float2half_rn(y0);
        hrow[tid + 256] = __float2half_rn(y1);
        hrow[tid + 512] = __float2half_rn(y2);
    }
}

// ---------------- launch ------------------------------------------------------
extern "C" void kernel_launch(void* const* d_in, const int* in_sizes, int n_in,
                              void* d_out, int out_size)
{
    const float* x      = (const float*)d_in[0];
    const float* enc    = (const float*)d_in[1];
    const float* ln1_g  = (const float*)d_in[2];
    const float* ln1_b  = (const float*)d_in[3];
    const float* qkv_w  = (const float*)d_in[4];
    const float* qkv_b  = (const float*)d_in[5];
    const float* proj_w = (const float*)d_in[6];
    const float* proj_b = (const float*)d_in[7];
    const float* ln2_g  = (const float*)d_in[8];
    const float* ln2_b  = (const float*)d_in[9];
    const float* caq_w  = (const float*)d_in[10];
    const float* caq_b  = (const float*)d_in[11];
    const float* cak_w  = (const float*)d_in[12];
    const float* cak_b  = (const float*)d_in[13];
    const float* cav_w  = (const float*)d_in[14];
    const float* cav_b  = (const float*)d_in[15];
    const float* cao_w  = (const float*)d_in[16];
    const float* cao_b  = (const float*)d_in[17];
    const float* ln3_g  = (const float*)d_in[18];
    const float* ln3_b  = (const float*)d_in[19];
    const float* fc_w   = (const float*)d_in[20];
    const float* fc_b   = (const float*)d_in[21];
    const float* fc2_w  = (const float*)d_in[22];
    const float* fc2_b  = (const float*)d_in[23];
    float* out = (float*)d_out;

    float *res, *x1, *x2;
    __half *x16, *enc16, *qkv16, *vt, *att16, *x1r, *x2r, *cq16, *ck16, *cvt, *h16;
    uint32_t *wq, *wp, *wcq, *wck, *wcv, *wco, *wfc, *wfc2;
    cudaGetSymbolAddress((void**)&res,   g_res);
    cudaGetSymbolAddress((void**)&x1,    g_x1);
    cudaGetSymbolAddress((void**)&x2,    g_x2);
    cudaGetSymbolAddress((void**)&x16,   g_x16);
    cudaGetSymbolAddress((void**)&enc16, g_enc16);
    cudaGetSymbolAddress((void**)&qkv16, g_qkv16);
    cudaGetSymbolAddress((void**)&vt,    g_vt);
    cudaGetSymbolAddress((void**)&att16, g_att16);
    cudaGetSymbolAddress((void**)&x1r,   g_x1r);
    cudaGetSymbolAddress((void**)&x2r,   g_x2r);
    cudaGetSymbolAddress((void**)&cq16,  g_cq16);
    cudaGetSymbolAddress((void**)&ck16,  g_ck16);
    cudaGetSymbolAddress((void**)&cvt,   g_cvt);
    cudaGetSymbolAddress((void**)&h16,   g_h16);
    cudaGetSymbolAddress((void**)&wq,    g_wq);
    cudaGetSymbolAddress((void**)&wp,    g_wp);
    cudaGetSymbolAddress((void**)&wcq,   g_wcq);
    cudaGetSymbolAddress((void**)&wck,   g_wck);
    cudaGetSymbolAddress((void**)&wcv,   g_wcv);
    cudaGetSymbolAddress((void**)&wco,   g_wco);
    cudaGetSymbolAddress((void**)&wfc,   g_wfc);
    cudaGetSymbolAddress((void**)&wfc2,  g_wfc2);

    cudaFuncSetAttribute(attn_h<true>,
                         cudaFuncAttributeMaxDynamicSharedMemorySize, AT_SMEM);
    cudaFuncSetAttribute(attn_h<false>,
                         cudaFuncAttributeMaxDynamicSharedMemorySize, AT_SMEM);
    cudaFuncSetAttribute((const void*)tgemm<4, EPI_NONE, OUT_QKV>,
                         cudaFuncAttributeMaxDynamicSharedMemorySize, GSMEM4);
    cudaFuncSetAttribute((const void*)tgemm<4, EPI_RELU, OUT_H>,
                         cudaFuncAttributeMaxDynamicSharedMemorySize, GSMEM4);
    cudaFuncSetAttribute((const void*)tgemm<2, EPI_RES, OUT_F32>,
                         cudaFuncAttributeMaxDynamicSharedMemorySize, GSMEM2);
    cudaFuncSetAttribute((const void*)tgemm3,
                         cudaFuncAttributeMaxDynamicSharedMemorySize, GSMEM4);

    const dim3 thr(256);
    const dim3 athr(128);
    const dim3 gqkv(3 * CC / 128, MROWS / 128);      // (18,32)
    const dim3 g768s(CC / 128, MROWS / 64);          // (6,64) MT=2
    const dim3 gfc(4 * CC / 128, MROWS / 128);       // (24,32)
    const dim3 g3(CC / 128, MROWS / 128, 3);         // (6,32,3)
    const dim3 gattn(TT / 64, HH, BB);               // (32,12,2) = 768

    // 0) merged pre-pass
    prepack<<<ACT_BLKS + 9216, thr>>>(x, enc, qkv_w, proj_w, caq_w, cak_w,
                                      cav_w, cao_w, fc_w, fc2_w,
                                      x16, enc16, wq, wp, wcq, wck, wcv, wco,
                                      wfc, wfc2);

    // 1) qkv (q,k rowmajor fp16 + V transposed)
    tgemm<4, EPI_NONE, OUT_QKV><<<gqkv, thr, GSMEM4>>>(x16, wq, qkv_b, nullptr,
                                                       nullptr, qkv16, vt,
                                                       MROWS, 3 * CC, CC);
    // 2) causal self-attention
    attn_h<true><<<gattn, athr, AT_SMEM>>>(qkv16, qkv16 + CC, vt, att16,
                                           3 * CC, 3 * CC);
    // 3) proj + residual ; LN1
    tgemm<2, EPI_RES, OUT_F32><<<g768s, thr, GSMEM2>>>(att16, wp, proj_b, x, res,
                                                       nullptr, nullptr,
                                                       MROWS, CC, CC);
    layernorm_k<<<MROWS, thr>>>(res, ln1_g, ln1_b, x1, x1r);

    // 4) cross projections (cv written transposed)
    tgemm3<<<g3, thr, GSMEM4>>>(x1r, enc16, wcq, caq_b, wck, cak_b,
                                wcv, cav_b, cq16, ck16, cvt);
    // 5) cross attention
    attn_h<false><<<gattn, athr, AT_SMEM>>>(cq16, ck16, cvt, att16, CC, CC);
    // 6) cao + residual ; LN2
    tgemm<2, EPI_RES, OUT_F32><<<g768s, thr, GSMEM2>>>(att16, wco, cao_b, x1, res,
                                                       nullptr, nullptr,
                                                       MROWS, CC, CC);
    layernorm_k<<<MROWS, thr>>>(res, ln2_g, ln2_b, x2, x2r);

    // 7) MLP
    tgemm<4, EPI_RELU, OUT_H><<<gfc, thr, GSMEM4>>>(x2r, wfc, fc_b, nullptr,
                                                    nullptr, h16, nullptr,
                                                    MROWS, 4 * CC, CC);
    tgemm<2, EPI_RES, OUT_F32><<<g768s, thr, GSMEM2>>>(h16, wfc2, fc2_b, x2, res,
                                                       nullptr, nullptr,
                                                       MROWS, CC, 4 * CC);
    // 8) LN3 -> out
    layernorm_k<<<MROWS, thr>>>(res, ln3_g, ln3_b, out, nullptr);
}

// round 17
// speedup vs baseline: 1.0346x; 1.0207x over previous
#include <cuda_runtime.h>
#include <cuda_fp16.h>
#include <math.h>
#include <stdint.h>

#define BB 2
#define TT 2048
#define CC 768
#define HH 12
#define DD 64
#define MROWS (BB*TT)   // 4096
#define L2E 1.4426950408889634f

// ---------------- scratch ----------------------------------------------------
__device__ float g_res[(size_t)MROWS * CC];
__device__ float g_x1 [(size_t)MROWS * CC];
__device__ float g_x2 [(size_t)MROWS * CC];
__device__ __half g_x16  [(size_t)MROWS * CC];
__device__ __half g_enc16[(size_t)MROWS * CC];
__device__ __half g_qkv16[(size_t)MROWS * 3 * CC];
__device__ __half g_vt   [(size_t)BB * HH * DD * TT];   // V transposed [b][h][d][t]
__device__ __half g_att16[(size_t)MROWS * CC];
__device__ __half g_x1r  [(size_t)MROWS * CC];
__device__ __half g_x2r  [(size_t)MROWS * CC];
__device__ __half g_cq16 [(size_t)MROWS * CC];
__device__ __half g_ck16 [(size_t)MROWS * CC];
__device__ __half g_cvt  [(size_t)BB * HH * DD * TT];   // cross V transposed
__device__ __half g_h16  [(size_t)MROWS * 4 * CC];
// fp16 weights TRANSPOSED to [N][K], k-pair-packed as u32 [N][K/2]
__device__ uint32_t g_wq  [(size_t)3*CC * CC/2];
__device__ uint32_t g_wp  [(size_t)CC * CC/2];
__device__ uint32_t g_wcq [(size_t)CC * CC/2];
__device__ uint32_t g_wck [(size_t)CC * CC/2];
__device__ uint32_t g_wcv [(size_t)CC * CC/2];
__device__ uint32_t g_wco [(size_t)CC * CC/2];
__device__ uint32_t g_wfc [(size_t)4*CC * CC/2];
__device__ uint32_t g_wfc2[(size_t)CC * 4*CC/2];

enum { EPI_NONE = 0, EPI_RELU = 1, EPI_RES = 2 };
enum { OUT_F32 = 0, OUT_H = 1, OUT_QKV = 2, OUT_HP = 3 };

__device__ __forceinline__ void cp16(uint32_t s, const void* g) {
    asm volatile("cp.async.cg.shared.global [%0], [%1], 16;" :: "r"(s), "l"(g));
}
__device__ __forceinline__ void ldsm4(uint32_t* d, uint32_t addr) {
    asm volatile("ldmatrix.sync.aligned.m8n8.x4.shared.b16 {%0,%1,%2,%3}, [%4];"
        : "=r"(d[0]), "=r"(d[1]), "=r"(d[2]), "=r"(d[3]) : "r"(addr));
}
__device__ __forceinline__ void mma_f16(float* d, const uint32_t* a,
                                        uint32_t b0, uint32_t b1) {
    asm volatile(
        "mma.sync.aligned.m16n8k16.row.col.f32.f16.f16.f32 "
        "{%0,%1,%2,%3}, {%4,%5,%6,%7}, {%8,%9}, {%0,%1,%2,%3};\n"
        : "+f"(d[0]), "+f"(d[1]), "+f"(d[2]), "+f"(d[3])
        : "r"(a[0]), "r"(a[1]), "r"(a[2]), "r"(a[3]), "r"(b0), "r"(b1));
}
__device__ __forceinline__ float ex2(float x) {
    float y;
    asm("ex2.approx.f32 %0, %1;" : "=f"(y) : "f"(x));
    return y;
}
__device__ __forceinline__ uint32_t ex2h2(uint32_t x) {
    uint32_t y;
    asm("ex2.approx.f16x2 %0, %1;" : "=r"(y) : "r"(x));
    return y;
}

// ---------------- merged pre-pass: act fp16 + weight transpose/pack ----------
#define S_X 1572864u
#define ACT_BLKS 12288u

__global__ __launch_bounds__(256)
void prepack(const float* x, const float* enc, const float* qw,
             const float* pw, const float* cqw, const float* ckw,
             const float* cvw, const float* cow, const float* fcw,
             const float* fc2w,
             __half* x16, __half* enc16, uint32_t* wq, uint32_t* wp,
             uint32_t* wcq, uint32_t* wck, uint32_t* wcv, uint32_t* wco,
             uint32_t* wfc, uint32_t* wfc2)
{
    __shared__ float s[32][33];
    if (blockIdx.x < ACT_BLKS) {
        const uint32_t i = blockIdx.x * 256u + threadIdx.x;
        const float* sp; __half* d; uint32_t l;
        if (i < S_X) { sp = x;   d = x16;   l = i; }
        else         { sp = enc; d = enc16; l = i - S_X; }
        const float2 v = *(const float2*)(sp + 2 * l);
        *(__half2*)(d + 2 * l) = __floats2half2_rn(v.x, v.y);
        return;
    }
    const uint32_t t = blockIdx.x - ACT_BLKS;
    const float* src; uint32_t* dst; uint32_t K, N, lt;
    if      (t < 1728u) { src = qw;   dst = wq;   K = 768;  N = 2304; lt = t; }
    else if (t < 2304u) { src = pw;   dst = wp;   K = 768;  N = 768;  lt = t - 1728u; }
    else if (t < 2880u) { src = cqw;  dst = wcq;  K = 768;  N = 768;  lt = t - 2304u; }
    else if (t < 3456u) { src = ckw;  dst = wck;  K = 768;  N = 768;  lt = t - 2880u; }
    else if (t < 4032u) { src = cvw;  dst = wcv;  K = 768;  N = 768;  lt = t - 3456u; }
    else if (t < 4608u) { src = cow;  dst = wco;  K = 768;  N = 768;  lt = t - 4032u; }
    else if (t < 6912u) { src = fcw;  dst = wfc;  K = 768;  N = 3072; lt = t - 4608u; }
    else                { src = fc2w; dst = wfc2; K = 3072; N = 768;  lt = t - 6912u; }
    const uint32_t KT = K >> 5;
    const uint32_t k0 = (lt % KT) << 5, n0 = (lt / KT) << 5;
    const int tx = threadIdx.x & 31, ty = threadIdx.x >> 5;
    #pragma unroll
    for (int j = 0; j < 4; j++)
        s[ty + j * 8][tx] = src[(size_t)(k0 + ty + j * 8) * N + n0 + tx];
    __syncthreads();
    #pragma unroll
    for (int j = 0; j < 2; j++) {
        const int idx = threadIdx.x + j * 256;
        const int n = idx >> 4, k2 = idx & 15;
        __half2 h = __floats2half2_rn(s[2 * k2][n], s[2 * k2 + 1][n]);
        dst[(size_t)(n0 + n) * (K >> 1) + (k0 >> 1) + k2] = *(uint32_t*)&h;
    }
}

// ---------------- fp16 GEMM (MT*32)x128x64, ldmatrix, NSTG-stage cp.async ----
template<int MT, int NSTG, int EPI, int OUT>
__device__ __forceinline__
void tgemm_body(uint32_t* sm, const __half* __restrict__ Ah,
                const uint32_t* __restrict__ Bt, const float* __restrict__ bias,
                const float* __restrict__ res, float* __restrict__ Cf,
                __half* __restrict__ Ch, __half* __restrict__ Vp,
                int M, int N, int K, int mBase, int nBase)
{
    constexpr int ABUF = MT * 32 * 36;
    constexpr int STG  = ABUF + 128 * 36;

    const int tid = threadIdx.x;
    const int lane = tid & 31, warp = tid >> 5;
    const int wm = warp >> 2, wn = warp & 3;
    const int r = lane >> 2, q = lane & 3;
    const int j8 = lane >> 3, t8 = lane & 7;
    const uint32_t smemBase = (uint32_t)__cvta_generic_to_shared(sm);
    const int K2 = K >> 1;

    float acc[MT][4][4];
    #pragma unroll
    for (int mt = 0; mt < MT; mt++)
        #pragma unroll
        for (int nt = 0; nt < 4; nt++)
            #pragma unroll
            for (int e = 0; e < 4; e++) acc[mt][nt][e] = 0.f;

    const int nchunk = K >> 6;

    auto issue = [&](int c) {
        if (c < nchunk) {
            const int kc = c << 6;
            const int kc2 = c << 5;
            const uint32_t sb = smemBase + (uint32_t)((c % NSTG) * STG * 4);
            #pragma unroll
            for (int i = 0; i < MT; i++) {
                const int fid = tid + (i << 8);
                const int row = fid >> 3, k4 = (fid & 7) << 2;
                cp16(sb + (uint32_t)((row * 36 + k4) * 4),
                     Ah + (size_t)(mBase + row) * K + kc + (fid & 7) * 8);
            }
            #pragma unroll
            for (int i = 0; i < 4; i++) {
                const int fid = tid + (i << 8);
                const int row = fid >> 3, k4 = (fid & 7) << 2;
                cp16(sb + (uint32_t)((ABUF + row * 36 + k4) * 4),
                     Bt + (size_t)(nBase + row) * K2 + kc2 + (fid & 7) * 4);
            }
        }
        asm volatile("cp.async.commit_group;");
    };

    #pragma unroll
    for (int p = 0; p < NSTG - 1; p++) issue(p);

    for (int c = 0; c < nchunk; c++) {
        asm volatile("cp.async.wait_group %0;" :: "n"(NSTG - 2));
        __syncthreads();
        issue(c + NSTG - 1);

        const uint32_t smA = smemBase + (uint32_t)((c % NSTG) * STG * 4);
        const uint32_t smB = smA + (uint32_t)(ABUF * 4);
        const uint32_t aBase = smA +
            (uint32_t)(((wm * (MT * 16) + (j8 & 1) * 8 + t8) * 36 + (j8 >> 1) * 4) * 4);
        const uint32_t bBase = smB +
            (uint32_t)(((wn * 32 + (j8 >> 1) * 8 + t8) * 36 + (j8 & 1) * 4) * 4);

        #pragma unroll
        for (int ks = 0; ks < 4; ks++) {
            uint32_t af[MT][4], bq[2][4];
            #pragma unroll
            for (int mt = 0; mt < MT; mt++)
                ldsm4(af[mt], aBase + (uint32_t)((mt * 16 * 36 + ks * 8) * 4));
            #pragma unroll
            for (int p = 0; p < 2; p++)
                ldsm4(bq[p], bBase + (uint32_t)((p * 16 * 36 + ks * 8) * 4));
            #pragma unroll
            for (int mt = 0; mt < MT; mt++)
                #pragma unroll
                for (int nt = 0; nt < 4; nt++)
                    mma_f16(acc[mt][nt], af[mt],
                            bq[nt >> 1][(nt & 1) * 2], bq[nt >> 1][(nt & 1) * 2 + 1]);
        }
    }

    #pragma unroll
    for (int mt = 0; mt < MT; mt++) {
        const int row0 = mBase + wm * (MT * 16) + mt * 16 + r;
        #pragma unroll
        for (int nt = 0; nt < 4; nt++) {
            const int col = nBase + wn * 32 + nt * 8 + 2 * q;
            const float2 bv = *(const float2*)(bias + col);
            float2 v0 = make_float2(acc[mt][nt][0] + bv.x, acc[mt][nt][1] + bv.y);
            float2 v1 = make_float2(acc[mt][nt][2] + bv.x, acc[mt][nt][3] + bv.y);
            if (EPI == EPI_RELU) {
                v0.x = fmaxf(v0.x, 0.f); v0.y = fmaxf(v0.y, 0.f);
                v1.x = fmaxf(v1.x, 0.f); v1.y = fmaxf(v1.y, 0.f);
            }
            if (EPI == EPI_RES) {
                const float2 r0 = *(const float2*)(res + (size_t)row0 * N + col);
                const float2 r1 = *(const float2*)(res + (size_t)(row0 + 8) * N + col);
                v0.x += r0.x; v0.y += r0.y;
                v1.x += r1.x; v1.y += r1.y;
            }
            if (OUT == OUT_F32) {
                *(float2*)(Cf + (size_t)row0 * N + col) = v0;
                *(float2*)(Cf + (size_t)(row0 + 8) * N + col) = v1;
            }
            if (OUT == OUT_H || OUT == OUT_QKV) {
                *(__half2*)(Ch + (size_t)row0 * N + col) = __floats2half2_rn(v0.x, v0.y);
                *(__half2*)(Ch + (size_t)(row0 + 8) * N + col) = __floats2half2_rn(v1.x, v1.y);
            }
            if ((OUT == OUT_QKV && nBase >= 2 * CC) || OUT == OUT_HP) {
                const int vc = (OUT == OUT_QKV ? col - 2 * CC : col);
                const int hh = vc >> 6, dd = vc & 63;
                const int bb = row0 >> 11, t = row0 & 2047;
                __half* vb = Vp + (((size_t)(bb * HH + hh) * DD + dd) << 11) + t;
                vb[0]      = __float2half_rn(v0.x);
                vb[TT]     = __float2half_rn(v0.y);
                vb[8]      = __float2half_rn(v1.x);
                vb[TT + 8] = __float2half_rn(v1.y);
            }
        }
    }
}

template<int MT, int NSTG, int OCC, int EPI, int OUT>
__global__ __launch_bounds__(256, OCC)
void tgemm(const __half* __restrict__ A, const uint32_t* __restrict__ Bt,
           const float* __restrict__ bias, const float* __restrict__ res,
           float* __restrict__ Cf, __half* __restrict__ Ch,
           __half* __restrict__ Vp, int M, int N, int K)
{
    extern __shared__ uint32_t sm32[];
    tgemm_body<MT, NSTG, EPI, OUT>(sm32, A, Bt, bias, res, Cf, Ch, Vp, M, N, K,
                                   blockIdx.y * (MT * 32), blockIdx.x * 128);
}

__global__ __launch_bounds__(256, 2)
void tgemm3(const __half* __restrict__ x1r, const __half* __restrict__ encr,
            const uint32_t* qw, const float* qb,
            const uint32_t* kw, const float* kb,
            const uint32_t* vw, const float* vb,
            __half* cq, __half* ck, __half* cvt)
{
    extern __shared__ uint32_t sm32[];
    const int z = blockIdx.z;
    const int mB = blockIdx.y * 128, nB = blockIdx.x * 128;
    if (z == 0)
        tgemm_body<4, 3, EPI_NONE, OUT_H>(sm32, x1r, qw, qb, nullptr, nullptr,
                                          cq, nullptr, MROWS, CC, CC, mB, nB);
    else if (z == 1)
        tgemm_body<4, 3, EPI_NONE, OUT_H>(sm32, encr, kw, kb, nullptr, nullptr,
                                          ck, nullptr, MROWS, CC, CC, mB, nB);
    else
        tgemm_body<4, 3, EPI_NONE, OUT_HP>(sm32, encr, vw, vb, nullptr, nullptr,
                                           nullptr, cvt, MROWS, CC, CC, mB, nB);
}

#define GSMEM4 (3*(4*32*36 + 128*36)*4)   // 110592 B (MT=4, 3 stg, 2 CTAs/SM)
#define GSMEM2 (2*(2*32*36 + 128*36)*4)   // 55296 B  (MT=2, 2 stg, 3 CTAs/SM)

// ---------------- fp16 flash attention: 64q tiles, 128 thr, 3 CTAs/SM --------
#define TQS 36
#define A_TSMKV 2304
#define A_TSTG 4608
#define AT_SMEM (16128*4)
#define ONESF 0x3C003C00u

template<bool CAUSAL>
__global__ __launch_bounds__(128, 3)
void attn_h(const __half* __restrict__ Q, const __half* __restrict__ Kp,
            const __half* __restrict__ Vt, __half* __restrict__ O,
            int qstride, int kstride)
{
    extern __shared__ uint32_t sm32[];
    const int b = blockIdx.z, h = blockIdx.y;
    const int qt = CAUSAL ? (gridDim.x - 1 - blockIdx.x) : blockIdx.x;
    const int tid = threadIdx.x;
    const int lane = tid & 31, warp = tid >> 5;
    const int r = lane >> 2, q = lane & 3;
    const int j8 = lane >> 3, t8 = lane & 7;
    const int qbase = qt * 64;
    const int qw16 = warp * 16;
    const uint32_t smemBase = (uint32_t)__cvta_generic_to_shared(sm32);

    const int nkt = CAUSAL ? (qt + 1) : (TT / 64);
    const __half* vtb = Vt + (((size_t)(b * HH + h) * DD) << 11);

    auto issueKV = [&](int kt) {
        if (kt < nkt) {
            const int kb = kt * 64;
            const uint32_t sb = smemBase + (uint32_t)((A_TSMKV + (kt % 3) * A_TSTG) * 4);
            #pragma unroll
            for (int i = 0; i < 4; i++) {
                const int lin = tid + (i << 7);
                const int row = lin >> 3, c8 = lin & 7;
                cp16(sb + (uint32_t)((row * 36 + c8 * 4) * 4),
                     Kp + (size_t)(b * TT + kb + row) * kstride + h * DD + c8 * 8);
            }
            #pragma unroll
            for (int i = 0; i < 4; i++) {
                const int lin = tid + (i << 7);
                const int row = lin >> 3, c8 = lin & 7;
                cp16(sb + (uint32_t)((2304 + row * 36 + c8 * 4) * 4),
                     vtb + ((size_t)row << 11) + kb + c8 * 8);
            }
        }
        asm volatile("cp.async.commit_group;");
    };

    issueKV(0);
    issueKV(1);

    uint32_t* Qs = sm32;
    const __half2 hscale = __floats2half2_rn(0.125f, 0.125f);
    #pragma unroll
    for (int i = 0; i < 4; i++) {
        const int lin = tid + (i << 7);
        const int row = lin >> 3, c8 = lin & 7;
        float4 v = *(const float4*)(Q + (size_t)(b * TT + qbase + row) * qstride
                                    + h * DD + c8 * 8);
        __half2* hv = (__half2*)&v;
        #pragma unroll
        for (int e = 0; e < 4; e++) hv[e] = __hmul2(hv[e], hscale);
        *(float4*)(Qs + row * TQS + c8 * 4) = v;
    }

    const uint32_t aQ = smemBase +
        (uint32_t)(((qw16 + (j8 & 1) * 8 + t8) * TQS + (j8 >> 1) * 4) * 4);
    const uint32_t bPat =
        (uint32_t)((((j8 >> 1) * 8 + t8) * 36 + (j8 & 1) * 4) * 4);

    float oacc[8][4], lacc[4];
    float m0 = -1e30f, m1 = -1e30f;
    #pragma unroll
    for (int nt = 0; nt < 8; nt++)
        #pragma unroll
        for (int e = 0; e < 4; e++) oacc[nt][e] = 0.f;
    #pragma unroll
    for (int e = 0; e < 4; e++) lacc[e] = 0.f;

    for (int kt = 0; kt < nkt; kt++) {
        asm volatile("cp.async.wait_group 1;");
        __syncthreads();
        issueKV(kt + 2);

        const uint32_t smK = smemBase + (uint32_t)((A_TSMKV + (kt % 3) * A_TSTG) * 4);
        const uint32_t smV = smK + 2304 * 4;
        const int kbase = kt * 64;

        float sacc[8][4];
        #pragma unroll
        for (int nt = 0; nt < 8; nt++)
            #pragma unroll
            for (int e = 0; e < 4; e++) sacc[nt][e] = 0.f;

        #pragma unroll
        for (int ks = 0; ks < 4; ks++) {
            uint32_t af[4], bk[4][4];
            ldsm4(af, aQ + (uint32_t)(ks * 32));
            #pragma unroll
            for (int p = 0; p < 4; p++)
                ldsm4(bk[p], smK + bPat + (uint32_t)((p * 16 * 36 + ks * 8) * 4));
            #pragma unroll
            for (int nt = 0; nt < 8; nt++)
                mma_f16(sacc[nt], af,
                        bk[nt >> 1][(nt & 1) * 2], bk[nt >> 1][(nt & 1) * 2 + 1]);
        }

        if (CAUSAL && kbase + 63 > qbase + qw16) {
            const int row0 = qbase + qw16 + r, row1 = row0 + 8;
            #pragma unroll
            for (int nt = 0; nt < 8; nt++) {
                const int c0 = kbase + nt * 8 + 2 * q, c1 = c0 + 1;
                if (c0 > row0) sacc[nt][0] = -1e30f;
                if (c1 > row0) sacc[nt][1] = -1e30f;
                if (c0 > row1) sacc[nt][2] = -1e30f;
                if (c1 > row1) sacc[nt][3] = -1e30f;
            }
        }

        float rm0 = -1e30f, rm1 = -1e30f;
        #pragma unroll
        for (int nt = 0; nt < 8; nt++) {
            rm0 = fmaxf(rm0, fmaxf(sacc[nt][0], sacc[nt][1]));
            rm1 = fmaxf(rm1, fmaxf(sacc[nt][2], sacc[nt][3]));
        }
        rm0 = fmaxf(rm0, __shfl_xor_sync(0xffffffffu, rm0, 1));
        rm0 = fmaxf(rm0, __shfl_xor_sync(0xffffffffu, rm0, 2));
        rm1 = fmaxf(rm1, __shfl_xor_sync(0xffffffffu, rm1, 1));
        rm1 = fmaxf(rm1, __shfl_xor_sync(0xffffffffu, rm1, 2));

        const float mn0 = fmaxf(m0, rm0), mn1 = fmaxf(m1, rm1);
        const float mnl0 = mn0 * L2E, mnl1 = mn1 * L2E;
        const float cr0 = ex2(fmaf(m0, L2E, -mnl0));
        const float cr1 = ex2(fmaf(m1, L2E, -mnl1));
        m0 = mn0; m1 = mn1;

        uint32_t ph[8][2];
        #pragma unroll
        for (int nt = 0; nt < 8; nt++) {
            __half2 h0 = __floats2half2_rn(fmaf(sacc[nt][0], L2E, -mnl0),
                                           fmaf(sacc[nt][1], L2E, -mnl0));
            __half2 h1 = __floats2half2_rn(fmaf(sacc[nt][2], L2E, -mnl1),
                                           fmaf(sacc[nt][3], L2E, -mnl1));
            ph[nt][0] = ex2h2(*(uint32_t*)&h0);
            ph[nt][1] = ex2h2(*(uint32_t*)&h1);
        }

        #pragma unroll
        for (int nt = 0; nt < 8; nt++) {
            oacc[nt][0] *= cr0; oacc[nt][1] *= cr0;
            oacc[nt][2] *= cr1; oacc[nt][3] *= cr1;
        }
        lacc[0] *= cr0; lacc[1] *= cr0; lacc[2] *= cr1; lacc[3] *= cr1;

        #pragma unroll
        for (int ks = 0; ks < 4; ks++) {
            uint32_t af[4], bv[4][4];
            af[0] = ph[2 * ks][0];
            af[1] = ph[2 * ks][1];
            af[2] = ph[2 * ks + 1][0];
            af[3] = ph[2 * ks + 1][1];
            #pragma unroll
            for (int p = 0; p < 4; p++)
                ldsm4(bv[p], smV + bPat + (uint32_t)((p * 16 * 36 + ks * 8) * 4));
            #pragma unroll
            for (int nt = 0; nt < 8; nt++)
                mma_f16(oacc[nt], af,
                        bv[nt >> 1][(nt & 1) * 2], bv[nt >> 1][(nt & 1) * 2 + 1]);
            mma_f16(lacc, af, ONESF, ONESF);
        }
    }

    const float inv0 = 1.f / lacc[0], inv1 = 1.f / lacc[2];
    const int row0 = qbase + qw16 + r;
    __half* og0 = O + (size_t)(b * TT + row0) * CC + h * DD + 2 * q;
    __half* og1 = O + (size_t)(b * TT + row0 + 8) * CC + h * DD + 2 * q;
    #pragma unroll
    for (int nt = 0; nt < 8; nt++) {
        *(__half2*)(og0 + nt * 8) = __floats2half2_rn(oacc[nt][0] * inv0,
                                                      oacc[nt][1] * inv0);
        *(__half2*)(og1 + nt * 8) = __floats2half2_rn(oacc[nt][2] * inv1,
                                                      oacc[nt][3] * inv1);
    }
}

// ---------------- LayerNorm ---------------------------------------------------
__global__ __launch_bounds__(256)
void layernorm_k(const float* __restrict__ in, const float* __restrict__ g,
                 const float* __restrict__ b, float* __restrict__ out,
                 __half* __restrict__ outh)
{
    const int row = blockIdx.x;
    const int tid = threadIdx.x;
    const float* x = in + (size_t)row * CC;

    const float v0 = x[tid], v1 = x[tid + 256], v2 = x[tid + 512];
    float s = v0 + v1 + v2;
    float sq = v0 * v0 + v1 * v1 + v2 * v2;

    #pragma unroll
    for (int off = 16; off; off >>= 1) {
        s  += __shfl_xor_sync(0xffffffffu, s, off);
        sq += __shfl_xor_sync(0xffffffffu, sq, off);
    }
    __shared__ float red[16];
    const int wid = tid >> 5, lane = tid & 31;
    if (lane == 0) { red[wid] = s; red[wid + 8] = sq; }
    __syncthreads();

    float ts = 0.f, tq = 0.f;
    #pragma unroll
    for (int i = 0; i < 8; i++) { ts += red[i]; tq += red[i + 8]; }

    const float mu = ts * (1.f / CC);
    const float var = tq * (1.f / CC) - mu * mu;
    const float rstd = rsqrtf(var + 1e-5f);

    const float y0 = (v0 - mu) * rstd * g[tid]       + b[tid];
    const float y1 = (v1 - mu) * rstd * g[tid + 256] + b[tid + 256];
    const float y2 = (v2 - mu) * rstd * g[tid + 512] + b[tid + 512];

    float* orow = out + (size_t)row * CC;
    orow[tid] = y0; orow[tid + 256] = y1; orow[tid + 512] = y2;
    if (outh) {
        __half* hrow = outh + (size_t)row * CC;
        hrow[tid]       = __float2half_rn(y0);
        hrow[tid + 256] = __float2half_rn(y1);
        hrow[tid + 512] = __float2half_rn(y2);
    }
}

// ---------------- launch ------------------------------------------------------
extern "C" void kernel_launch(void* const* d_in, const int* in_sizes, int n_in,
                              void* d_out, int out_size)
{
    const float* x      = (const float*)d_in[0];
    const float* enc    = (const float*)d_in[1];
    const float* ln1_g  = (const float*)d_in[2];
    const float* ln1_b  = (const float*)d_in[3];
    const float* qkv_w  = (const float*)d_in[4];
    const float* qkv_b  = (const float*)d_in[5];
    const float* proj_w = (const float*)d_in[6];
    const float* proj_b = (const float*)d_in[7];
    const float* ln2_g  = (const float*)d_in[8];
    const float* ln2_b  = (const float*)d_in[9];
    const float* caq_w  = (const float*)d_in[10];
    const float* caq_b  = (const float*)d_in[11];
    const float* cak_w  = (const float*)d_in[12];
    const float* cak_b  = (const float*)d_in[13];
    const float* cav_w  = (const float*)d_in[14];
    const float* cav_b  = (const float*)d_in[15];
    const float* cao_w  = (const float*)d_in[16];
    const float* cao_b  = (const float*)d_in[17];
    const float* ln3_g  = (const float*)d_in[18];
    const float* ln3_b  = (const float*)d_in[19];
    const float* fc_w   = (const float*)d_in[20];
    const float* fc_b   = (const float*)d_in[21];
    const float* fc2_w  = (const float*)d_in[22];
    const float* fc2_b  = (const float*)d_in[23];
    float* out = (float*)d_out;

    float *res, *x1, *x2;
    __half *x16, *enc16, *qkv16, *vt, *att16, *x1r, *x2r, *cq16, *ck16, *cvt, *h16;
    uint32_t *wq, *wp, *wcq, *wck, *wcv, *wco, *wfc, *wfc2;
    cudaGetSymbolAddress((void**)&res,   g_res);
    cudaGetSymbolAddress((void**)&x1,    g_x1);
    cudaGetSymbolAddress((void**)&x2,    g_x2);
    cudaGetSymbolAddress((void**)&x16,   g_x16);
    cudaGetSymbolAddress((void**)&enc16, g_enc16);
    cudaGetSymbolAddress((void**)&qkv16, g_qkv16);
    cudaGetSymbolAddress((void**)&vt,    g_vt);
    cudaGetSymbolAddress((void**)&att16, g_att16);
    cudaGetSymbolAddress((void**)&x1r,   g_x1r);
    cudaGetSymbolAddress((void**)&x2r,   g_x2r);
    cudaGetSymbolAddress((void**)&cq16,  g_cq16);
    cudaGetSymbolAddress((void**)&ck16,  g_ck16);
    cudaGetSymbolAddress((void**)&cvt,   g_cvt);
    cudaGetSymbolAddress((void**)&h16,   g_h16);
    cudaGetSymbolAddress((void**)&wq,    g_wq);
    cudaGetSymbolAddress((void**)&wp,    g_wp);
    cudaGetSymbolAddress((void**)&wcq,   g_wcq);
    cudaGetSymbolAddress((void**)&wck,   g_wck);
    cudaGetSymbolAddress((void**)&wcv,   g_wcv);
    cudaGetSymbolAddress((void**)&wco,   g_wco);
    cudaGetSymbolAddress((void**)&wfc,   g_wfc);
    cudaGetSymbolAddress((void**)&wfc2,  g_wfc2);

    cudaFuncSetAttribute(attn_h<true>,
                         cudaFuncAttributeMaxDynamicSharedMemorySize, AT_SMEM);
    cudaFuncSetAttribute(attn_h<false>,
                         cudaFuncAttributeMaxDynamicSharedMemorySize, AT_SMEM);
    cudaFuncSetAttribute((const void*)tgemm<4, 3, 2, EPI_NONE, OUT_QKV>,
                         cudaFuncAttributeMaxDynamicSharedMemorySize, GSMEM4);
    cudaFuncSetAttribute((const void*)tgemm<4, 3, 2, EPI_RELU, OUT_H>,
                         cudaFuncAttributeMaxDynamicSharedMemorySize, GSMEM4);
    cudaFuncSetAttribute((const void*)tgemm<2, 2, 3, EPI_RES, OUT_F32>,
                         cudaFuncAttributeMaxDynamicSharedMemorySize, GSMEM2);
    cudaFuncSetAttribute((const void*)tgemm3,
                         cudaFuncAttributeMaxDynamicSharedMemorySize, GSMEM4);

    const dim3 thr(256);
    const dim3 athr(128);
    const dim3 gqkv(3 * CC / 128, MROWS / 128);      // (18,32)
    const dim3 g768s(CC / 128, MROWS / 64);          // (6,64) MT=2
    const dim3 gfc(4 * CC / 128, MROWS / 128);       // (24,32)
    const dim3 g3(CC / 128, MROWS / 128, 3);         // (6,32,3)
    const dim3 gattn(TT / 64, HH, BB);               // (32,12,2) = 768

    // 0) merged pre-pass
    prepack<<<ACT_BLKS + 9216, thr>>>(x, enc, qkv_w, proj_w, caq_w, cak_w,
                                      cav_w, cao_w, fc_w, fc2_w,
                                      x16, enc16, wq, wp, wcq, wck, wcv, wco,
                                      wfc, wfc2);

    // 1) qkv (q,k rowmajor fp16 + V transposed)
    tgemm<4, 3, 2, EPI_NONE, OUT_QKV><<<gqkv, thr, GSMEM4>>>(
        x16, wq, qkv_b, nullptr, nullptr, qkv16, vt, MROWS, 3 * CC, CC);
    // 2) causal self-attention
    attn_h<true><<<gattn, athr, AT_SMEM>>>(qkv16, qkv16 + CC, vt, att16,
                                           3 * CC, 3 * CC);
    // 3) proj + residual ; LN1
    tgemm<2, 2, 3, EPI_RES, OUT_F32><<<g768s, thr, GSMEM2>>>(
        att16, wp, proj_b, x, res, nullptr, nullptr, MROWS, CC, CC);
    layernorm_k<<<MROWS, thr>>>(res, ln1_g, ln1_b, x1, x1r);

    // 4) cross projections (cv written transposed)
    tgemm3<<<g3, thr, GSMEM4>>>(x1r, enc16, wcq, caq_b, wck, cak_b,
                                wcv, cav_b, cq16, ck16, cvt);
    // 5) cross attention
    attn_h<false><<<gattn, athr, AT_SMEM>>>(cq16, ck16, cvt, att16, CC, CC);
    // 6) cao + residual ; LN2
    tgemm<2, 2, 3, EPI_RES, OUT_F32><<<g768s, thr, GSMEM2>>>(
        att16, wco, cao_b, x1, res, nullptr, nullptr, MROWS, CC, CC);
    layernorm_k<<<MROWS, thr>>>(res, ln2_g, ln2_b, x2, x2r);

    // 7) MLP
    tgemm<4, 3, 2, EPI_RELU, OUT_H><<<gfc, thr, GSMEM4>>>(
        x2r, wfc, fc_b, nullptr, nullptr, h16, nullptr, MROWS, 4 * CC, CC);
    tgemm<2, 2, 3, EPI_RES, OUT_F32><<<g768s, thr, GSMEM2>>>(
        h16, wfc2, fc2_b, x2, res, nullptr, nullptr, MROWS, CC, 4 * CC);
    // 8) LN3 -> out
    layernorm_k<<<MROWS, thr>>>(res, ln3_g, ln3_b, out, nullptr);
}